// round 1
// baseline (speedup 1.0000x reference)
#include <cuda_runtime.h>

static constexpr int BB  = 65536;
static constexpr int DD  = 512;
static constexpr int KK  = 64;
static constexpr int HH1 = 256;
static constexpr int HH2 = 128;

// Scratch (static device globals: allocation-guard-safe)
__device__ float g_h1[BB * HH1];   // 64 MB
__device__ float g_h2[BB * HH2];   // 32 MB
__device__ float g_xt[BB * KK];    // 16 MB

// ---------------------------------------------------------------------------
// Generic fp32 SGEMM: C[M,N] = A[M,K] @ B[K,N] (+bias, +relu)
// Block tile 64x64, 256 threads, 4x4 per-thread tile, K-chunk 16.
// M,N multiples of 64; K multiple of 16 (true for all three calls).
// ---------------------------------------------------------------------------
template<bool RELU, bool BIAS>
__global__ __launch_bounds__(256)
void sgemm_kernel(const float* __restrict__ A, const float* __restrict__ Bm,
                  const float* __restrict__ bias, float* __restrict__ C,
                  int N, int K)
{
    __shared__ float As[16][68];   // transposed A tile, padded (row = k)
    __shared__ float Bs[16][64];

    const int m0 = blockIdx.y * 64;
    const int n0 = blockIdx.x * 64;
    const int t  = threadIdx.x;
    const int tx = t & 15;         // 0..15 -> 4 N columns each
    const int ty = t >> 4;         // 0..15 -> 4 M rows each

    float acc[4][4];
#pragma unroll
    for (int i = 0; i < 4; i++)
#pragma unroll
        for (int j = 0; j < 4; j++) acc[i][j] = 0.f;

    // A tile load mapping: thread t loads float4 at (row = t/4, k = (t%4)*4)
    const int a_row = t >> 2;
    const int a_k   = (t & 3) * 4;
    // B tile load mapping: thread t loads column n = t%64 at k rows t/64 + {0,4,8,12}
    const int b_n = t & 63;
    const int b_k = t >> 6;

    const float* Arow = A + (m0 + a_row) * K;

    const int ntiles = K >> 4;
    for (int kt = 0; kt < ntiles; kt++) {
        const int kbase = kt << 4;

        float4 av = *(const float4*)(Arow + kbase + a_k);
        As[a_k + 0][a_row] = av.x;
        As[a_k + 1][a_row] = av.y;
        As[a_k + 2][a_row] = av.z;
        As[a_k + 3][a_row] = av.w;

#pragma unroll
        for (int r = 0; r < 4; r++) {
            const int kk2 = b_k + r * 4;
            Bs[kk2][b_n] = Bm[(kbase + kk2) * N + n0 + b_n];
        }
        __syncthreads();

#pragma unroll
        for (int k = 0; k < 16; k++) {
            float4 a4 = *(const float4*)&As[k][ty * 4];
            float4 b4 = *(const float4*)&Bs[k][tx * 4];
            float ar[4] = {a4.x, a4.y, a4.z, a4.w};
            float br[4] = {b4.x, b4.y, b4.z, b4.w};
#pragma unroll
            for (int i = 0; i < 4; i++)
#pragma unroll
                for (int j = 0; j < 4; j++)
                    acc[i][j] = fmaf(ar[i], br[j], acc[i][j]);
        }
        __syncthreads();
    }

    // Epilogue: bias + relu + float4 store
#pragma unroll
    for (int i = 0; i < 4; i++) {
        const int row = m0 + ty * 4 + i;
        float4 v;
        float* vv = (float*)&v;
#pragma unroll
        for (int j = 0; j < 4; j++) {
            float c = acc[i][j];
            if (BIAS) c += bias[n0 + tx * 4 + j];
            if (RELU) c = fmaxf(c, 0.f);
            vv[j] = c;
        }
        *(float4*)(C + row * N + n0 + tx * 4) = v;
    }
}

// ---------------------------------------------------------------------------
// Tail: logits = h2 @ W3 + b3 ; gumbel softmax ; selected = <xt, w> ;
// loss partial = (selected-label)^2 / B -> atomicAdd into out.
// One thread per row; W3 staged in smem (warp-uniform broadcast reads).
// ---------------------------------------------------------------------------
__global__ __launch_bounds__(256)
void finalize_kernel(const float* __restrict__ label, const float* __restrict__ u,
                     const float* __restrict__ W3, const float* __restrict__ b3,
                     const int* __restrict__ epoch_p, float* __restrict__ out)
{
    __shared__ float sW3[HH2 * KK];   // 32 KB
    __shared__ float sb3[KK];
    __shared__ float red[8];

    for (int i = threadIdx.x; i < HH2 * KK; i += 256) sW3[i] = W3[i];
    if (threadIdx.x < KK) sb3[threadIdx.x] = b3[threadIdx.x];
    __syncthreads();

    const int row = blockIdx.x * 256 + threadIdx.x;

    float v[64];
#pragma unroll
    for (int j = 0; j < 64; j++) v[j] = sb3[j];

    // logits: 128 x 64 GEMV per row; W3 reads are warp-uniform (broadcast)
    const float*  h2r = g_h2 + row * HH2;
    const float4* sW4 = (const float4*)sW3;
#pragma unroll 4
    for (int i = 0; i < HH2; i++) {
        const float h = h2r[i];
        const float4* wr = sW4 + i * 16;
#pragma unroll
        for (int j4 = 0; j4 < 16; j4++) {
            float4 w = wr[j4];
            v[j4 * 4 + 0] = fmaf(h, w.x, v[j4 * 4 + 0]);
            v[j4 * 4 + 1] = fmaf(h, w.y, v[j4 * 4 + 1]);
            v[j4 * 4 + 2] = fmaf(h, w.z, v[j4 * 4 + 2]);
            v[j4 * 4 + 3] = fmaf(h, w.w, v[j4 * 4 + 3]);
        }
    }

    // temperature schedule
    const float ep = (float)(*epoch_p);
    float temp = 10.0f * expf(logf(0.01f) * ep * 0.001f);
    temp = fmaxf(0.1f, temp);
    const float tinv = 1.0f / temp;

    // gumbel + scaled logits, running max
    const float* ur = u + row * KK;
    float mx = -1e30f;
#pragma unroll
    for (int j = 0; j < 64; j++) {
        float g = -__logf(-__logf(ur[j]));
        float s = (v[j] + g) * tinv;
        v[j] = s;
        mx = fmaxf(mx, s);
    }
    // softmax
    float sum = 0.f;
#pragma unroll
    for (int j = 0; j < 64; j++) {
        float e = __expf(v[j] - mx);
        v[j] = e;
        sum += e;
    }
    const float rs = 1.0f / sum;

    // selected = <xt_row, weights>
    const float* xtr = g_xt + row * KK;
    float sel = 0.f;
#pragma unroll
    for (int j = 0; j < 64; j++) sel = fmaf(xtr[j], v[j] * rs, sel);

    float d = sel - label[row];
    float p = d * d * (1.0f / (float)BB);

    // block reduction
#pragma unroll
    for (int o = 16; o; o >>= 1) p += __shfl_xor_sync(0xffffffffu, p, o);
    if ((threadIdx.x & 31) == 0) red[threadIdx.x >> 5] = p;
    __syncthreads();
    if (threadIdx.x < 8) {
        p = red[threadIdx.x];
#pragma unroll
        for (int o = 4; o; o >>= 1) p += __shfl_xor_sync(0xffu, p, o);
        if (threadIdx.x == 0) atomicAdd(out, p);
    }
}

// ---------------------------------------------------------------------------
extern "C" void kernel_launch(void* const* d_in, const int* in_sizes, int n_in,
                              void* d_out, int out_size)
{
    const float* x      = (const float*)d_in[0];
    const float* label  = (const float*)d_in[1];
    const float* u      = (const float*)d_in[2];
    const float* W1     = (const float*)d_in[3];
    const float* b1     = (const float*)d_in[4];
    const float* W2     = (const float*)d_in[5];
    const float* b2     = (const float*)d_in[6];
    const float* W3     = (const float*)d_in[7];
    const float* b3     = (const float*)d_in[8];
    const float* thetas = (const float*)d_in[9];
    const int*   epoch  = (const int*)d_in[10];
    float* out = (float*)d_out;

    float *h1p, *h2p, *xtp;
    cudaGetSymbolAddress((void**)&h1p, g_h1);
    cudaGetSymbolAddress((void**)&h2p, g_h2);
    cudaGetSymbolAddress((void**)&xtp, g_xt);

    cudaMemsetAsync(out, 0, (size_t)out_size * sizeof(float), 0);

    // h1 = relu(x @ W1 + b1)         [65536, 256]
    sgemm_kernel<true, true><<<dim3(HH1 / 64, BB / 64), 256>>>(x, W1, b1, h1p, HH1, DD);
    // xt = x @ thetas                 [65536, 64]
    sgemm_kernel<false, false><<<dim3(KK / 64, BB / 64), 256>>>(x, thetas, nullptr, xtp, KK, DD);
    // h2 = relu(h1 @ W2 + b2)        [65536, 128]
    sgemm_kernel<true, true><<<dim3(HH2 / 64, BB / 64), 256>>>(h1p, W2, b2, h2p, HH2, HH1);
    // logits + gumbel softmax + loss
    finalize_kernel<<<BB / 256, 256>>>(label, u, W3, b3, epoch, out);
}

// round 3
// speedup vs baseline: 4.8994x; 4.8994x over previous
#include <cuda_runtime.h>
#include <cuda_bf16.h>
#include <cstdint>

#ifndef __CUDA_ARCH_HAS_FEATURE__
#define __CUDA_ARCH_HAS_FEATURE__(x) 0
#endif
#if defined(__CUDA_ARCH_FEAT_SM103_ALL) || __CUDA_ARCH_HAS_FEATURE__(SM103_ALL) || \
    defined(__CUDA_ARCH_FEAT_SM100_ALL) || __CUDA_ARCH_HAS_FEATURE__(SM100_ALL)
#define HAS_TCGEN05 1
#else
#define HAS_TCGEN05 0
#endif

static constexpr int BB  = 65536;
static constexpr int DD  = 512;
static constexpr int KK  = 64;
static constexpr int HH1 = 256;
static constexpr int HH2 = 128;

// ---------------- scratch (device globals: allocation-guard-safe) ----------
__device__ __nv_bfloat16 g_h1b[(size_t)BB * HH1];   // 32 MB
__device__ __nv_bfloat16 g_h2b[(size_t)BB * HH2];   // 16 MB
__device__ float         g_xt [(size_t)BB * KK];    // 16 MB
__device__ __nv_bfloat16 g_w1t[HH1 * DD];
__device__ __nv_bfloat16 g_w2t[HH2 * HH1];
__device__ __nv_bfloat16 g_w3t[KK * HH2];
__device__ __nv_bfloat16 g_tt [KK * DD];

// ---------------- PTX helpers ----------------------------------------------
__device__ __forceinline__ uint32_t smem_u32(const void* p) {
    uint32_t a;
    asm("{ .reg .u64 t; cvta.to.shared.u64 t, %1; cvt.u32.u64 %0, t; }" : "=r"(a) : "l"(p));
    return a;
}
__device__ __forceinline__ uint32_t elect_one() {
    uint32_t pred;
    asm volatile("{\n\t.reg .pred p;\n\telect.sync _|p, 0xFFFFFFFF;\n\tselp.b32 %0, 1, 0, p;\n\t}" : "=r"(pred));
    return pred;
}
#define MBAR_INIT(addr, cnt) \
    asm volatile("mbarrier.init.shared.b64 [%0], %1;" :: "r"(addr), "r"(cnt) : "memory")
#define MBAR_WAIT(addr, parity) do {                                              \
    asm volatile("{\n\t.reg .pred P;\n\tWL%=:\n\t"                                \
        "mbarrier.try_wait.parity.acquire.cta.shared::cta.b64 P, [%0], %1, 0x989680;\n\t" \
        "@P bra.uni WD%=;\n\tbra.uni WL%=;\n\tWD%=:\n\t}"                          \
        :: "r"(addr), "r"(parity) : "memory");                                    \
} while (0)
#define TC_ALLOC(smem_dst, n) \
    asm volatile("tcgen05.alloc.cta_group::1.sync.aligned.shared::cta.b32 [%0], %1;" :: "r"(smem_dst), "r"(n) : "memory")
#define TC_DEALLOC(tmem, n) \
    asm volatile("tcgen05.dealloc.cta_group::1.sync.aligned.b32 %0, %1;" :: "r"(tmem), "r"(n))
#define TC_RELINQ() \
    asm volatile("tcgen05.relinquish_alloc_permit.cta_group::1.sync.aligned;")
#define TC_COMMIT(mbar) \
    asm volatile("tcgen05.commit.cta_group::1.mbarrier::arrive::one.shared::cluster.b64 [%0];" :: "r"(mbar) : "memory")
#define TC_FENCE_AFTER()  asm volatile("tcgen05.fence::after_thread_sync;" ::: "memory")
#define TC_WAIT_LD()      asm volatile("tcgen05.wait::ld.sync.aligned;" ::: "memory")

#define TC_LD_X32(r, tmem_addr) \
    asm volatile( \
        "tcgen05.ld.sync.aligned.32x32b.x32.b32 " \
        "{%0, %1, %2, %3, %4, %5, %6, %7, " \
        " %8, %9, %10, %11, %12, %13, %14, %15, " \
        " %16, %17, %18, %19, %20, %21, %22, %23, " \
        " %24, %25, %26, %27, %28, %29, %30, %31}, [%32];" \
        : "=r"((r)[0]),  "=r"((r)[1]),  "=r"((r)[2]),  "=r"((r)[3]), \
          "=r"((r)[4]),  "=r"((r)[5]),  "=r"((r)[6]),  "=r"((r)[7]), \
          "=r"((r)[8]),  "=r"((r)[9]),  "=r"((r)[10]), "=r"((r)[11]), \
          "=r"((r)[12]), "=r"((r)[13]), "=r"((r)[14]), "=r"((r)[15]), \
          "=r"((r)[16]), "=r"((r)[17]), "=r"((r)[18]), "=r"((r)[19]), \
          "=r"((r)[20]), "=r"((r)[21]), "=r"((r)[22]), "=r"((r)[23]), \
          "=r"((r)[24]), "=r"((r)[25]), "=r"((r)[26]), "=r"((r)[27]), \
          "=r"((r)[28]), "=r"((r)[29]), "=r"((r)[30]), "=r"((r)[31]) \
        : "r"(tmem_addr))

#if HAS_TCGEN05
__device__ __forceinline__ void mma_f16_ss(uint32_t d, uint64_t ad, uint64_t bd,
                                           uint32_t idesc, uint32_t en) {
    asm volatile(
        "{\n\t.reg .pred p;\n\tsetp.ne.u32 p, %4, 0;\n\t"
        "tcgen05.mma.cta_group::1.kind::f16 [%0], %1, %2, %3, {%5, %5, %5, %5}, p;\n\t}"
        :: "r"(d), "l"(ad), "l"(bd), "r"(idesc), "r"(en), "r"(0u) : "memory");
}
#endif

__device__ __forceinline__ uint64_t make_desc(uint32_t addr) {
    const uint64_t base = (2ull << 61) | (1ull << 46) | (64ull << 32) | (1ull << 16); // SW128, LBO=1, SBO=64
    return base | ((uint64_t)(addr >> 4) & 0x3FFF);
}
__device__ __forceinline__ uint32_t sw128(uint32_t o) { return o ^ ((o >> 3) & 0x70); }

__device__ __forceinline__ uint32_t pack_bf2(float a, float b) {
    uint32_t r;
    asm("cvt.rn.satfinite.bf16x2.f32 %0, %1, %2;" : "=r"(r) : "f"(b), "f"(a)); // low = a
    return r;
}

static __host__ __device__ constexpr uint32_t idesc_n(int N) {
    return (1u << 4) | (1u << 7) | (1u << 10) | ((uint32_t)(N / 8) << 17) | (8u << 24); // M=128 bf16->f32
}

__device__ __forceinline__ float temp_of(float ep) {
    float t = 10.0f * expf(logf(0.01f) * ep * 0.001f);
    return fmaxf(0.1f, t);
}

// ---------------- weight transpose + bf16 convert ---------------------------
__global__ void transpose_bf16_k(const float* __restrict__ in,
                                 __nv_bfloat16* __restrict__ out, int R, int C) {
    int idx = blockIdx.x * 256 + threadIdx.x;
    if (idx < R * C) {
        int r = idx / C, c = idx - r * C;
        out[(size_t)c * R + r] = __float2bfloat16(in[idx]);
    }
}

// ---------------- tcgen05 GEMM (M-tile 128, K-chunk 64, double buffered) ----
// MODE 0: A = x (fp32, convert), B = [W1t(256) | thetas_t(64)], K=512
//         epilogue: h1 = relu(D+b1) -> bf16 ; xt = D[256..319] -> fp32
// MODE 1: A = h1b (bf16), B = W2t, N=128, K=256, epilogue relu+bias -> bf16
// MODE 2: A = h2b (bf16), B = W3t, N=64,  K=128, epilogue = gumbel softmax loss
template <int MODE>
__global__ __launch_bounds__(256, 1) void gemm_tc(
    const float* __restrict__ Afp, const __nv_bfloat16* __restrict__ Abf,
    const __nv_bfloat16* __restrict__ Bt, const __nv_bfloat16* __restrict__ Tt,
    const float* __restrict__ bias,
    __nv_bfloat16* __restrict__ OutBf, float* __restrict__ OutF,
    const float* __restrict__ u, const float* __restrict__ xt,
    const float* __restrict__ label, const int* __restrict__ epochp)
{
    constexpr int KTOT  = (MODE == 0) ? 512 : (MODE == 1) ? 256 : 128;
    constexpr int NB    = (MODE == 0) ? 256 : (MODE == 1) ? 128 : 64;
    constexpr int NT    = (MODE == 0) ? 64 : 0;
    constexpr int NBTOT = NB + NT;

#if HAS_TCGEN05
    constexpr int TCOLS = (MODE == 0) ? 512 : (MODE == 1) ? 128 : 64;
    constexpr int NC    = KTOT / 64;
    constexpr uint32_t IDB = idesc_n(NB);
    constexpr uint32_t IDT = idesc_n(64);

    constexpr uint32_t AOFF0 = 1024, AOFF1 = 1024 + 16384;
    constexpr uint32_t BOFF0 = 33792, BOFF1 = BOFF0 + (uint32_t)NBTOT * 128;
    constexpr uint32_t MBAR0 = 8;
    constexpr int B_UNITS = NBTOT * 8;

    extern __shared__ char smem[];
    const uint32_t sb = smem_u32(smem);
    const int tid = threadIdx.x;
    const int wid = tid >> 5;
    const int lane = tid & 31;
    const int m0 = blockIdx.x * 128;

    if (wid == 0) TC_ALLOC(sb + 0, TCOLS);
    if (tid == 0) { MBAR_INIT(sb + MBAR0, 1); MBAR_INIT(sb + MBAR0 + 8, 1); }
    __syncthreads();
    uint32_t tmem;
    asm volatile("ld.shared.b32 %0, [%1];" : "=r"(tmem) : "r"(sb + 0));

    for (int c = 0; c < NC; c++) {
        const int bufsel = c & 1;
        const uint32_t aoff = bufsel ? AOFF1 : AOFF0;
        const uint32_t boff = bufsel ? BOFF1 : BOFF0;
        if (c >= 2) MBAR_WAIT(sb + MBAR0 + 8 * bufsel, ((c - 2) >> 1) & 1);

        // ---- load A tile (128 x 64 bf16) ----
        if (MODE == 0) {
#pragma unroll
            for (int i = 0; i < 4; i++) {
                int q = tid + i * 256;
                int row = q >> 3, ku = q & 7;
                const float4* src = (const float4*)(Afp + (size_t)(m0 + row) * KTOT + c * 64 + ku * 8);
                float4 f0 = src[0], f1 = src[1];
                uint4 v;
                v.x = pack_bf2(f0.x, f0.y); v.y = pack_bf2(f0.z, f0.w);
                v.z = pack_bf2(f1.x, f1.y); v.w = pack_bf2(f1.z, f1.w);
                *(uint4*)(smem + aoff + sw128(row * 128 + ku * 16)) = v;
            }
        } else {
#pragma unroll
            for (int i = 0; i < 4; i++) {
                int q = tid + i * 256;
                int row = q >> 3, ku = q & 7;
                uint4 v = *(const uint4*)(Abf + (size_t)(m0 + row) * KTOT + c * 64 + ku * 8);
                *(uint4*)(smem + aoff + sw128(row * 128 + ku * 16)) = v;
            }
        }
        // ---- load B tile (NBTOT x 64 bf16) ----
        for (int q = tid; q < B_UNITS; q += 256) {
            int row = q >> 3, ku = q & 7;
            const __nv_bfloat16* src =
                (MODE == 0 && row >= NB) ? (Tt + (size_t)(row - NB) * KTOT) : (Bt + (size_t)row * KTOT);
            uint4 v = *(const uint4*)(src + c * 64 + ku * 8);
            *(uint4*)(smem + boff + sw128(row * 128 + ku * 16)) = v;
        }
        asm volatile("fence.proxy.async.shared::cta;" ::: "memory");
        __syncthreads();

        // ---- issue MMAs ----
        if (wid == 0) {
            if (elect_one()) {
                uint64_t ad = make_desc(sb + aoff);
                uint64_t bd = make_desc(sb + boff);
#pragma unroll
                for (int s = 0; s < 4; s++) {
                    uint32_t en = (c > 0 || s > 0) ? 1u : 0u;
                    mma_f16_ss(tmem, ad + 2 * s, bd + 2 * s, IDB, en);
                    if (MODE == 0)
                        mma_f16_ss(tmem + 256, ad + 2 * s,
                                   make_desc(sb + boff + (uint32_t)NB * 128) + 2 * s, IDT, en);
                }
                TC_COMMIT(sb + MBAR0 + 8 * bufsel);
            }
        }
        __syncwarp();
    }

    // wait for last chunk's MMAs
    MBAR_WAIT(sb + MBAR0 + 8 * ((NC - 1) & 1), ((NC - 1) >> 1) & 1);
    TC_FENCE_AFTER();

    const int sub = wid & 3;
    const int row = m0 + sub * 32 + lane;

    if (MODE == 0 || MODE == 1) {
        const int cb0 = (wid < 4) ? 0 : NB / 2;
        const int nch = NB / 64;           // 32-col chunks per warp-half
#pragma unroll
        for (int ch = 0; ch < nch; ch++) {
            const int cb = cb0 + ch * 32;
            uint32_t r[32];
            TC_LD_X32(r, tmem + cb);
            TC_WAIT_LD();
            uint32_t pk[16];
#pragma unroll
            for (int i = 0; i < 16; i++) {
                float a = __uint_as_float(r[2 * i + 0]) + __ldg(&bias[cb + 2 * i + 0]);
                float b = __uint_as_float(r[2 * i + 1]) + __ldg(&bias[cb + 2 * i + 1]);
                a = fmaxf(a, 0.f); b = fmaxf(b, 0.f);
                pk[i] = pack_bf2(a, b);
            }
            uint4* dst = (uint4*)(OutBf + (size_t)row * NB + cb);
#pragma unroll
            for (int k = 0; k < 4; k++)
                dst[k] = make_uint4(pk[4 * k], pk[4 * k + 1], pk[4 * k + 2], pk[4 * k + 3]);
        }
        if (MODE == 0 && wid >= 4) {       // xt -> fp32
#pragma unroll
            for (int ch = 0; ch < 2; ch++) {
                uint32_t r[32];
                TC_LD_X32(r, tmem + 256 + ch * 32);
                TC_WAIT_LD();
                float4* dst = (float4*)(OutF + (size_t)row * 64 + ch * 32);
#pragma unroll
                for (int k = 0; k < 8; k++)
                    dst[k] = make_float4(__uint_as_float(r[4 * k]), __uint_as_float(r[4 * k + 1]),
                                         __uint_as_float(r[4 * k + 2]), __uint_as_float(r[4 * k + 3]));
            }
        }
    } else { // MODE 2: finalize
        float p = 0.f;
        if (wid < 4) {
            float d[64];
            {
                uint32_t r[32];
                TC_LD_X32(r, tmem);
                TC_WAIT_LD();
#pragma unroll
                for (int j = 0; j < 32; j++) d[j] = __uint_as_float(r[j]);
                TC_LD_X32(r, tmem + 32);
                TC_WAIT_LD();
#pragma unroll
                for (int j = 0; j < 32; j++) d[32 + j] = __uint_as_float(r[j]);
            }
#pragma unroll
            for (int j = 0; j < 64; j++) d[j] += __ldg(&bias[j]);

            const float tinv = 1.0f / temp_of((float)(*epochp));

            const float4* up = (const float4*)(u + (size_t)row * 64);
            float mx = -1e30f;
#pragma unroll
            for (int q = 0; q < 16; q++) {
                float4 ug = up[q];
                d[4 * q + 0] = (d[4 * q + 0] - __logf(-__logf(ug.x))) * 0.f + (d[4 * q + 0] + -__logf(-__logf(ug.x))) * tinv;
                d[4 * q + 1] = (d[4 * q + 1] + -__logf(-__logf(ug.y))) * tinv;
                d[4 * q + 2] = (d[4 * q + 2] + -__logf(-__logf(ug.z))) * tinv;
                d[4 * q + 3] = (d[4 * q + 3] + -__logf(-__logf(ug.w))) * tinv;
                mx = fmaxf(mx, fmaxf(fmaxf(d[4 * q], d[4 * q + 1]), fmaxf(d[4 * q + 2], d[4 * q + 3])));
            }
            float sum = 0.f;
#pragma unroll
            for (int j = 0; j < 64; j++) { d[j] = __expf(d[j] - mx); sum += d[j]; }
            const float rs = 1.0f / sum;

            const float4* xp = (const float4*)(xt + (size_t)row * 64);
            float sel = 0.f;
#pragma unroll
            for (int q = 0; q < 16; q++) {
                float4 xg = xp[q];
                sel = fmaf(xg.x, d[4 * q + 0] * rs, sel);
                sel = fmaf(xg.y, d[4 * q + 1] * rs, sel);
                sel = fmaf(xg.z, d[4 * q + 2] * rs, sel);
                sel = fmaf(xg.w, d[4 * q + 3] * rs, sel);
            }
            float diff = sel - __ldg(&label[row]);
            p = diff * diff * (1.0f / (float)BB);
        }
#pragma unroll
        for (int o = 16; o; o >>= 1) p += __shfl_xor_sync(0xffffffffu, p, o);
        float* red = (float*)(smem + 128);
        if (lane == 0) red[wid] = p;
        __syncthreads();
        if (tid == 0) {
            float s = 0.f;
#pragma unroll
            for (int w = 0; w < 8; w++) s += red[w];
            atomicAdd(OutF, s);
        }
    }

    __syncthreads();
    if (wid == 0) { TC_RELINQ(); TC_DEALLOC(tmem, TCOLS); }

#else  // ------------------- SIMT fallback (generic PTX pass only) ---------
    const int tid = threadIdx.x;
    const int m0 = blockIdx.x * 128;
    if (MODE == 0 || MODE == 1) {
        for (int idx = tid; idx < 128 * NBTOT; idx += 256) {
            int r = idx / NBTOT, n = idx - r * NBTOT;
            float acc = 0.f;
            if (MODE == 0) {
                const float* a = Afp + (size_t)(m0 + r) * KTOT;
                const __nv_bfloat16* b = (n < NB) ? (Bt + (size_t)n * KTOT)
                                                  : (Tt + (size_t)(n - NB) * KTOT);
                for (int k = 0; k < KTOT; k++)
                    acc += __bfloat162float(__float2bfloat16(a[k])) * __bfloat162float(b[k]);
            } else {
                const __nv_bfloat16* a = Abf + (size_t)(m0 + r) * KTOT;
                const __nv_bfloat16* b = Bt + (size_t)n * KTOT;
                for (int k = 0; k < KTOT; k++)
                    acc += __bfloat162float(a[k]) * __bfloat162float(b[k]);
            }
            if (n < NB) {
                acc = fmaxf(acc + bias[n], 0.f);
                OutBf[(size_t)(m0 + r) * NB + n] = __float2bfloat16(acc);
            } else {
                OutF[(size_t)(m0 + r) * 64 + (n - NB)] = acc;
            }
        }
    } else {
        __shared__ float red[8];
        float p = 0.f;
        if (tid < 128) {
            const int row = m0 + tid;
            float d[64];
            const __nv_bfloat16* a = Abf + (size_t)row * KTOT;
            for (int j = 0; j < 64; j++) {
                float acc = bias[j];
                const __nv_bfloat16* b = Bt + (size_t)j * KTOT;
                for (int k = 0; k < KTOT; k++)
                    acc += __bfloat162float(a[k]) * __bfloat162float(b[k]);
                d[j] = acc;
            }
            const float tinv = 1.0f / temp_of((float)(*epochp));
            float mx = -1e30f;
            for (int j = 0; j < 64; j++) {
                float g = -__logf(-__logf(u[(size_t)row * 64 + j]));
                d[j] = (d[j] + g) * tinv;
                mx = fmaxf(mx, d[j]);
            }
            float sum = 0.f;
            for (int j = 0; j < 64; j++) { d[j] = __expf(d[j] - mx); sum += d[j]; }
            float rs = 1.0f / sum, sel = 0.f;
            for (int j = 0; j < 64; j++) sel = fmaf(xt[(size_t)row * 64 + j], d[j] * rs, sel);
            float diff = sel - label[row];
            p = diff * diff * (1.0f / (float)BB);
        }
        for (int o = 16; o; o >>= 1) p += __shfl_xor_sync(0xffffffffu, p, o);
        if ((tid & 31) == 0) red[tid >> 5] = p;
        __syncthreads();
        if (tid == 0) {
            float s = 0.f;
            for (int w = 0; w < 8; w++) s += red[w];
            atomicAdd(OutF, s);
        }
    }
#endif
}

// ---------------------------------------------------------------------------
extern "C" void kernel_launch(void* const* d_in, const int* in_sizes, int n_in,
                              void* d_out, int out_size)
{
    const float* x      = (const float*)d_in[0];
    const float* label  = (const float*)d_in[1];
    const float* u      = (const float*)d_in[2];
    const float* W1     = (const float*)d_in[3];
    const float* b1     = (const float*)d_in[4];
    const float* W2     = (const float*)d_in[5];
    const float* b2     = (const float*)d_in[6];
    const float* W3     = (const float*)d_in[7];
    const float* b3     = (const float*)d_in[8];
    const float* thetas = (const float*)d_in[9];
    const int*   epoch  = (const int*)d_in[10];
    float* out = (float*)d_out;

    __nv_bfloat16 *h1b, *h2b, *w1t, *w2t, *w3t, *tt;
    float* xtp;
    cudaGetSymbolAddress((void**)&h1b, g_h1b);
    cudaGetSymbolAddress((void**)&h2b, g_h2b);
    cudaGetSymbolAddress((void**)&xtp, g_xt);
    cudaGetSymbolAddress((void**)&w1t, g_w1t);
    cudaGetSymbolAddress((void**)&w2t, g_w2t);
    cudaGetSymbolAddress((void**)&w3t, g_w3t);
    cudaGetSymbolAddress((void**)&tt,  g_tt);

    constexpr int SM0 = 33792 + 2 * 320 * 128;  // 115712
    constexpr int SM1 = 33792 + 2 * 128 * 128;  // 66560
    constexpr int SM2 = 33792 + 2 * 64 * 128;   // 50176
    cudaFuncSetAttribute(gemm_tc<0>, cudaFuncAttributeMaxDynamicSharedMemorySize, SM0);
    cudaFuncSetAttribute(gemm_tc<1>, cudaFuncAttributeMaxDynamicSharedMemorySize, SM1);
    cudaFuncSetAttribute(gemm_tc<2>, cudaFuncAttributeMaxDynamicSharedMemorySize, SM2);

    cudaMemsetAsync(out, 0, (size_t)out_size * sizeof(float), 0);

    transpose_bf16_k<<<(DD * HH1 + 255) / 256, 256>>>(W1, w1t, DD, HH1);
    transpose_bf16_k<<<(HH1 * HH2 + 255) / 256, 256>>>(W2, w2t, HH1, HH2);
    transpose_bf16_k<<<(HH2 * KK + 255) / 256, 256>>>(W3, w3t, HH2, KK);
    transpose_bf16_k<<<(DD * KK + 255) / 256, 256>>>(thetas, tt, DD, KK);

    gemm_tc<0><<<BB / 128, 256, SM0>>>(x, nullptr, w1t, tt, b1, h1b, xtp,
                                       nullptr, nullptr, nullptr, nullptr);
    gemm_tc<1><<<BB / 128, 256, SM1>>>(nullptr, h1b, w2t, nullptr, b2, h2b, nullptr,
                                       nullptr, nullptr, nullptr, nullptr);
    gemm_tc<2><<<BB / 128, 256, SM2>>>(nullptr, h2b, w3t, nullptr, b3, nullptr, out,
                                       u, xtp, label, epoch);
}

// round 4
// speedup vs baseline: 7.1481x; 1.4590x over previous
#include <cuda_runtime.h>
#include <cuda_bf16.h>
#include <cstdint>

#ifndef __CUDA_ARCH_HAS_FEATURE__
#define __CUDA_ARCH_HAS_FEATURE__(x) 0
#endif
#if defined(__CUDA_ARCH_FEAT_SM103_ALL) || __CUDA_ARCH_HAS_FEATURE__(SM103_ALL) || \
    defined(__CUDA_ARCH_FEAT_SM100_ALL) || __CUDA_ARCH_HAS_FEATURE__(SM100_ALL)
#define HAS_TCGEN05 1
#else
#define HAS_TCGEN05 0
#endif

static constexpr int BB  = 65536;
static constexpr int DD  = 512;
static constexpr int KK  = 64;
static constexpr int HH1 = 256;
static constexpr int HH2 = 128;

// ---------------- scratch (device globals: allocation-guard-safe) ----------
__device__ __nv_bfloat16 g_w1t[HH1 * DD];   // [n][k] K-major
__device__ __nv_bfloat16 g_w2t[HH2 * HH1];
__device__ __nv_bfloat16 g_w3t[KK * HH2];
__device__ __nv_bfloat16 g_tt [KK * DD];

// ---------------- PTX helpers ----------------------------------------------
__device__ __forceinline__ uint32_t smem_u32(const void* p) {
    uint32_t a;
    asm("{ .reg .u64 t; cvta.to.shared.u64 t, %1; cvt.u32.u64 %0, t; }" : "=r"(a) : "l"(p));
    return a;
}
__device__ __forceinline__ uint32_t elect_one() {
    uint32_t pred;
    asm volatile("{\n\t.reg .pred p;\n\telect.sync _|p, 0xFFFFFFFF;\n\tselp.b32 %0, 1, 0, p;\n\t}" : "=r"(pred));
    return pred;
}
#define MBAR_INIT(addr, cnt) \
    asm volatile("mbarrier.init.shared.b64 [%0], %1;" :: "r"(addr), "r"(cnt) : "memory")
#define MBAR_WAIT(addr, parity) do {                                              \
    asm volatile("{\n\t.reg .pred P;\n\tWL%=:\n\t"                                \
        "mbarrier.try_wait.parity.acquire.cta.shared::cta.b64 P, [%0], %1, 0x989680;\n\t" \
        "@P bra.uni WD%=;\n\tbra.uni WL%=;\n\tWD%=:\n\t}"                          \
        :: "r"(addr), "r"(parity) : "memory");                                    \
} while (0)
#define TC_ALLOC(smem_dst, n) \
    asm volatile("tcgen05.alloc.cta_group::1.sync.aligned.shared::cta.b32 [%0], %1;" :: "r"(smem_dst), "r"(n) : "memory")
#define TC_DEALLOC(tmem, n) \
    asm volatile("tcgen05.dealloc.cta_group::1.sync.aligned.b32 %0, %1;" :: "r"(tmem), "r"(n))
#define TC_RELINQ() \
    asm volatile("tcgen05.relinquish_alloc_permit.cta_group::1.sync.aligned;")
#define TC_COMMIT(mbar) \
    asm volatile("tcgen05.commit.cta_group::1.mbarrier::arrive::one.shared::cluster.b64 [%0];" :: "r"(mbar) : "memory")
#define TC_FENCE_AFTER()  asm volatile("tcgen05.fence::after_thread_sync;" ::: "memory")
#define TC_WAIT_LD()      asm volatile("tcgen05.wait::ld.sync.aligned;" ::: "memory")

#define TC_LD_X32(r, tmem_addr) \
    asm volatile( \
        "tcgen05.ld.sync.aligned.32x32b.x32.b32 " \
        "{%0, %1, %2, %3, %4, %5, %6, %7, " \
        " %8, %9, %10, %11, %12, %13, %14, %15, " \
        " %16, %17, %18, %19, %20, %21, %22, %23, " \
        " %24, %25, %26, %27, %28, %29, %30, %31}, [%32];" \
        : "=r"((r)[0]),  "=r"((r)[1]),  "=r"((r)[2]),  "=r"((r)[3]), \
          "=r"((r)[4]),  "=r"((r)[5]),  "=r"((r)[6]),  "=r"((r)[7]), \
          "=r"((r)[8]),  "=r"((r)[9]),  "=r"((r)[10]), "=r"((r)[11]), \
          "=r"((r)[12]), "=r"((r)[13]), "=r"((r)[14]), "=r"((r)[15]), \
          "=r"((r)[16]), "=r"((r)[17]), "=r"((r)[18]), "=r"((r)[19]), \
          "=r"((r)[20]), "=r"((r)[21]), "=r"((r)[22]), "=r"((r)[23]), \
          "=r"((r)[24]), "=r"((r)[25]), "=r"((r)[26]), "=r"((r)[27]), \
          "=r"((r)[28]), "=r"((r)[29]), "=r"((r)[30]), "=r"((r)[31]) \
        : "r"(tmem_addr))

#if HAS_TCGEN05
__device__ __forceinline__ void mma_f16_ss(uint32_t d, uint64_t ad, uint64_t bd,
                                           uint32_t idesc, uint32_t en) {
    asm volatile(
        "{\n\t.reg .pred p;\n\tsetp.ne.u32 p, %4, 0;\n\t"
        "tcgen05.mma.cta_group::1.kind::f16 [%0], %1, %2, %3, {%5, %5, %5, %5}, p;\n\t}"
        :: "r"(d), "l"(ad), "l"(bd), "r"(idesc), "r"(en), "r"(0u) : "memory");
}
#endif

__device__ __forceinline__ uint64_t make_desc(uint32_t addr) {
    const uint64_t base = (2ull << 61) | (1ull << 46) | (64ull << 32) | (1ull << 16); // SW128, LBO=1, SBO=64
    return base | ((uint64_t)(addr >> 4) & 0x3FFF);
}
__device__ __forceinline__ uint32_t sw128(uint32_t o) { return o ^ ((o >> 3) & 0x70); }

__device__ __forceinline__ uint32_t pack_bf2(float a, float b) {
    uint32_t r;
    asm("cvt.rn.satfinite.bf16x2.f32 %0, %1, %2;" : "=r"(r) : "f"(b), "f"(a)); // low = a
    return r;
}

static __host__ __device__ constexpr uint32_t idesc_n(int N) {
    return (1u << 4) | (1u << 7) | (1u << 10) | ((uint32_t)(N / 8) << 17) | (8u << 24); // M=128 bf16->f32
}

__device__ __forceinline__ float temp_of(float ep) {
    float t = 10.0f * expf(logf(0.01f) * ep * 0.001f);
    return fmaxf(0.1f, t);
}

// ---------------- fused weight transpose + bf16 convert (one launch) --------
__global__ void transpose_all(const float* __restrict__ W1, const float* __restrict__ W2,
                              const float* __restrict__ W3, const float* __restrict__ Th,
                              __nv_bfloat16* __restrict__ w1t, __nv_bfloat16* __restrict__ w2t,
                              __nv_bfloat16* __restrict__ w3t, __nv_bfloat16* __restrict__ tt)
{
    int idx = blockIdx.x * 256 + threadIdx.x;
    // segment sizes: 131072 | 32768 | 8192 | 32768
    if (idx < 131072) {
        int r = idx >> 8, c = idx & 255;                       // W1: 512x256
        w1t[c * DD + r] = __float2bfloat16(W1[idx]);
    } else if (idx < 163840) {
        int q = idx - 131072; int r = q >> 7, c = q & 127;     // W2: 256x128
        w2t[c * HH1 + r] = __float2bfloat16(W2[q]);
    } else if (idx < 172032) {
        int q = idx - 163840; int r = q >> 6, c = q & 63;      // W3: 128x64
        w3t[c * HH2 + r] = __float2bfloat16(W3[q]);
    } else if (idx < 204800) {
        int q = idx - 172032; int r = q >> 6, c = q & 63;      // thetas: 512x64
        tt[c * DD + r] = __float2bfloat16(Th[q]);
    }
}

// ---------------- fully fused kernel ---------------------------------------
// Per CTA (M-tile = 128 rows):
//  P1: x @ [W1t|tt] -> TMEM h1 (cols 0..255) + xt (cols 256..319)
//  P2: h1 epilogue (bias+relu) -> SMEM A-tile ; load W2t
//  P3: MMA -> h2 (TMEM 320..447)
//  P4: h2 epilogue -> SMEM A-tile ; load W3t
//  P5: MMA -> logits (TMEM 448..511)
//  P6: gumbel softmax + <xt, w> + MSE -> atomicAdd(out)
__global__ __launch_bounds__(256, 1) void fused_llp(
    const float* __restrict__ x, const float* __restrict__ u,
    const float* __restrict__ label,
    const __nv_bfloat16* __restrict__ w1t, const __nv_bfloat16* __restrict__ w2t,
    const __nv_bfloat16* __restrict__ w3t, const __nv_bfloat16* __restrict__ tt,
    const float* __restrict__ b1, const float* __restrict__ b2,
    const float* __restrict__ b3, const int* __restrict__ epochp,
    float* __restrict__ out)
{
#if HAS_TCGEN05
    constexpr uint32_t MB0 = 8, MB1 = 16, MB2 = 24;
    constexpr uint32_t RED = 32;
    constexpr uint32_t AOFF0 = 1024, AOFF1 = 17408;       // 16KB each
    constexpr uint32_t BOFF0 = 33792, BOFF1 = 74752;      // 40KB each (320x64)
    constexpr uint32_t H1TILE = 1024;                     // 64KB  (4 blk of 128x64)
    constexpr uint32_t W2T   = 66560;                     // 64KB
    constexpr uint32_t H2TILE = 1024;                     // 32KB  (2 blk)
    constexpr uint32_t W3T   = 33792;                     // 16KB  (2 blk of 64x64)
    constexpr uint32_t IDB1 = idesc_n(256), IDT = idesc_n(64);
    constexpr uint32_t IDB2 = idesc_n(128), IDB3 = idesc_n(64);
    constexpr uint32_t T_H1 = 0, T_XT = 256, T_H2 = 320, T_LG = 448;

    extern __shared__ char smem[];
    const uint32_t sb = smem_u32(smem);
    const int tid = threadIdx.x;
    const int wid = tid >> 5;
    const int lane = tid & 31;
    const int m0 = blockIdx.x * 128;

    if (wid == 0) TC_ALLOC(sb + 0, 512);
    if (tid == 0) { MBAR_INIT(sb + MB0, 1); MBAR_INIT(sb + MB1, 1); MBAR_INIT(sb + MB2, 1); }
    __syncthreads();
    uint32_t tmem;
    asm volatile("ld.shared.b32 %0, [%1];" : "=r"(tmem) : "r"(sb + 0));

    // ================= Phase 1: x @ [W1t | tt], K=512, 8 chunks ===========
    for (int c = 0; c < 8; c++) {
        const int bufsel = c & 1;
        const uint32_t aoff = bufsel ? AOFF1 : AOFF0;
        const uint32_t boff = bufsel ? BOFF1 : BOFF0;
        if (c >= 2) MBAR_WAIT(sb + MB0 + 8 * bufsel, ((c - 2) >> 1) & 1);

        // A: x chunk 128x64 fp32 -> bf16
#pragma unroll
        for (int i = 0; i < 4; i++) {
            int q = tid + i * 256;
            int row = q >> 3, ku = q & 7;
            const float4* src = (const float4*)(x + (size_t)(m0 + row) * DD + c * 64 + ku * 8);
            float4 f0 = src[0], f1 = src[1];
            uint4 v;
            v.x = pack_bf2(f0.x, f0.y); v.y = pack_bf2(f0.z, f0.w);
            v.z = pack_bf2(f1.x, f1.y); v.w = pack_bf2(f1.z, f1.w);
            *(uint4*)(smem + aoff + sw128(row * 128 + ku * 16)) = v;
        }
        // B: [W1t rows 0..255 | tt rows 0..63] chunk, 320x64
        for (int q = tid; q < 320 * 8; q += 256) {
            int row = q >> 3, ku = q & 7;
            const __nv_bfloat16* src = (row >= 256) ? (tt + (size_t)(row - 256) * DD)
                                                    : (w1t + (size_t)row * DD);
            uint4 v = *(const uint4*)(src + c * 64 + ku * 8);
            *(uint4*)(smem + boff + sw128(row * 128 + ku * 16)) = v;
        }
        asm volatile("fence.proxy.async.shared::cta;" ::: "memory");
        __syncthreads();

        if (wid == 0 && elect_one()) {
            uint64_t ad = make_desc(sb + aoff);
            uint64_t bd = make_desc(sb + boff);
            uint64_t td = make_desc(sb + boff + 256 * 128);
#pragma unroll
            for (int s = 0; s < 4; s++) {
                uint32_t en = (c > 0 || s > 0) ? 1u : 0u;
                mma_f16_ss(tmem + T_H1, ad + 2 * s, bd + 2 * s, IDB1, en);
                mma_f16_ss(tmem + T_XT, ad + 2 * s, td + 2 * s, IDT, en);
            }
            TC_COMMIT(sb + MB0 + 8 * bufsel);
        }
        __syncwarp();
    }
    MBAR_WAIT(sb + MB1, 1);   // chunk 7 = 4th commit on mbar1 -> parity 1
    TC_FENCE_AFTER();
    __syncthreads();          // all MMA reads of A/B buffers done; safe to reuse smem

    // ================= Phase 2: h1 epilogue -> SMEM ; load W2t ============
    {
        const int sub = wid & 3;
        const int row = sub * 32 + lane;
        const int cb0 = (wid < 4) ? 0 : 128;
#pragma unroll
        for (int ch = 0; ch < 4; ch++) {
            const int cb = cb0 + ch * 32;
            uint32_t r[32];
            TC_LD_X32(r, tmem + T_H1 + cb);
            TC_WAIT_LD();
            uint32_t pk[16];
#pragma unroll
            for (int i = 0; i < 16; i++) {
                float a = __uint_as_float(r[2 * i + 0]) + __ldg(&b1[cb + 2 * i + 0]);
                float b = __uint_as_float(r[2 * i + 1]) + __ldg(&b1[cb + 2 * i + 1]);
                pk[i] = pack_bf2(fmaxf(a, 0.f), fmaxf(b, 0.f));
            }
            const uint32_t blk = (uint32_t)(cb >> 6) * 16384u;
            const uint32_t base = (uint32_t)row * 128 + (uint32_t)(cb & 63) * 2;
#pragma unroll
            for (int k = 0; k < 4; k++)
                *(uint4*)(smem + H1TILE + blk + sw128(base + k * 16)) =
                    make_uint4(pk[4 * k], pk[4 * k + 1], pk[4 * k + 2], pk[4 * k + 3]);
        }
        // W2t: 128 rows x 256 cols -> 4 K-blocks of 128x64
        for (int q = tid; q < 128 * 32; q += 256) {
            int n = q >> 5, t = q & 31, blk = t >> 3, ku = t & 7;
            uint4 v = *(const uint4*)(w2t + (size_t)n * HH1 + blk * 64 + ku * 8);
            *(uint4*)(smem + W2T + blk * 16384 + sw128(n * 128 + ku * 16)) = v;
        }
    }
    asm volatile("fence.proxy.async.shared::cta;" ::: "memory");
    __syncthreads();

    // ================= Phase 3: h1 @ W2t -> h2, K=256 =====================
    if (wid == 0 && elect_one()) {
        uint64_t ad = make_desc(sb + H1TILE);
        uint64_t bd = make_desc(sb + W2T);
#pragma unroll
        for (int s = 0; s < 16; s++) {
            uint64_t off = (uint64_t)(s >> 2) * 1024 + (s & 3) * 2;
            mma_f16_ss(tmem + T_H2, ad + off, bd + off, IDB2, s > 0 ? 1u : 0u);
        }
        TC_COMMIT(sb + MB2);
    }
    MBAR_WAIT(sb + MB2, 0);
    TC_FENCE_AFTER();
    __syncthreads();

    // ================= Phase 4: h2 epilogue -> SMEM ; load W3t ============
    {
        const int sub = wid & 3;
        const int row = sub * 32 + lane;
        const int cb0 = (wid < 4) ? 0 : 64;
#pragma unroll
        for (int ch = 0; ch < 2; ch++) {
            const int cb = cb0 + ch * 32;
            uint32_t r[32];
            TC_LD_X32(r, tmem + T_H2 + cb);
            TC_WAIT_LD();
            uint32_t pk[16];
#pragma unroll
            for (int i = 0; i < 16; i++) {
                float a = __uint_as_float(r[2 * i + 0]) + __ldg(&b2[cb + 2 * i + 0]);
                float b = __uint_as_float(r[2 * i + 1]) + __ldg(&b2[cb + 2 * i + 1]);
                pk[i] = pack_bf2(fmaxf(a, 0.f), fmaxf(b, 0.f));
            }
            const uint32_t blk = (uint32_t)(cb >> 6) * 16384u;
            const uint32_t base = (uint32_t)row * 128 + (uint32_t)(cb & 63) * 2;
#pragma unroll
            for (int k = 0; k < 4; k++)
                *(uint4*)(smem + H2TILE + blk + sw128(base + k * 16)) =
                    make_uint4(pk[4 * k], pk[4 * k + 1], pk[4 * k + 2], pk[4 * k + 3]);
        }
        // W3t: 64 rows x 128 cols -> 2 K-blocks of 64x64 (8KB each)
        for (int q = tid; q < 64 * 16; q += 256) {
            int n = q >> 4, t = q & 15, blk = t >> 3, ku = t & 7;
            uint4 v = *(const uint4*)(w3t + (size_t)n * HH2 + blk * 64 + ku * 8);
            *(uint4*)(smem + W3T + blk * 8192 + sw128(n * 128 + ku * 16)) = v;
        }
    }
    asm volatile("fence.proxy.async.shared::cta;" ::: "memory");
    __syncthreads();

    // ================= Phase 5: h2 @ W3t -> logits, K=128 =================
    if (wid == 0 && elect_one()) {
        uint64_t ad = make_desc(sb + H2TILE);
        uint64_t bd = make_desc(sb + W3T);
#pragma unroll
        for (int s = 0; s < 8; s++) {
            uint64_t aoff = (uint64_t)(s >> 2) * 1024 + (s & 3) * 2;
            uint64_t boff = (uint64_t)(s >> 2) * 512 + (s & 3) * 2;
            mma_f16_ss(tmem + T_LG, ad + aoff, bd + boff, IDB3, s > 0 ? 1u : 0u);
        }
        TC_COMMIT(sb + MB2);
    }
    MBAR_WAIT(sb + MB2, 1);
    TC_FENCE_AFTER();

    // ================= Phase 6: finalize ==================================
    float p = 0.f;
    if (wid < 4) {
        const int row = m0 + (wid & 3) * 32 + lane;
        float d[64];
        {
            uint32_t r[32];
            TC_LD_X32(r, tmem + T_LG);
            TC_WAIT_LD();
#pragma unroll
            for (int j = 0; j < 32; j++) d[j] = __uint_as_float(r[j]);
            TC_LD_X32(r, tmem + T_LG + 32);
            TC_WAIT_LD();
#pragma unroll
            for (int j = 0; j < 32; j++) d[32 + j] = __uint_as_float(r[j]);
        }
#pragma unroll
        for (int j = 0; j < 64; j++) d[j] += __ldg(&b3[j]);

        const float tinv = 1.0f / temp_of((float)(*epochp));

        const float4* up = (const float4*)(u + (size_t)row * 64);
        float mx = -1e30f;
#pragma unroll
        for (int q = 0; q < 16; q++) {
            float4 ug = up[q];
            d[4 * q + 0] = (d[4 * q + 0] - __logf(-__logf(ug.x))) * tinv;
            d[4 * q + 1] = (d[4 * q + 1] - __logf(-__logf(ug.y))) * tinv;
            d[4 * q + 2] = (d[4 * q + 2] - __logf(-__logf(ug.z))) * tinv;
            d[4 * q + 3] = (d[4 * q + 3] - __logf(-__logf(ug.w))) * tinv;
            mx = fmaxf(mx, fmaxf(fmaxf(d[4 * q], d[4 * q + 1]), fmaxf(d[4 * q + 2], d[4 * q + 3])));
        }
        float sum = 0.f;
#pragma unroll
        for (int j = 0; j < 64; j++) { d[j] = __expf(d[j] - mx); sum += d[j]; }
        const float rs = 1.0f / sum;

        float xt[64];
        {
            uint32_t r[32];
            TC_LD_X32(r, tmem + T_XT);
            TC_WAIT_LD();
#pragma unroll
            for (int j = 0; j < 32; j++) xt[j] = __uint_as_float(r[j]);
            TC_LD_X32(r, tmem + T_XT + 32);
            TC_WAIT_LD();
#pragma unroll
            for (int j = 0; j < 32; j++) xt[32 + j] = __uint_as_float(r[j]);
        }
        float sel = 0.f;
#pragma unroll
        for (int j = 0; j < 64; j++) sel = fmaf(xt[j], d[j] * rs, sel);

        float diff = sel - __ldg(&label[row]);
        p = diff * diff * (1.0f / (float)BB);
    }
#pragma unroll
    for (int o = 16; o; o >>= 1) p += __shfl_xor_sync(0xffffffffu, p, o);
    {
        float* red = (float*)(smem + RED);
        if (wid < 4 && lane == 0) red[wid] = p;
        __syncthreads();
        if (tid == 0) atomicAdd(out, red[0] + red[1] + red[2] + red[3]);
    }

    __syncthreads();
    if (wid == 0) { TC_RELINQ(); TC_DEALLOC(tmem, 512); }

#else  // ------------------- SIMT fallback (generic PTX pass only) ---------
    __shared__ float red[8];
    const int tid = threadIdx.x;
    const int m0 = blockIdx.x * 128;
    float p = 0.f;
    if (tid < 128) {
        const int row = m0 + tid;
        float h1[256], h2[128], d[64];
        for (int n = 0; n < 256; n++) {
            float acc = b1[n];
            const __nv_bfloat16* w = w1t + (size_t)n * DD;
            for (int k = 0; k < DD; k++)
                acc += __bfloat162float(__float2bfloat16(x[(size_t)row * DD + k])) * __bfloat162float(w[k]);
            h1[n] = fmaxf(acc, 0.f);
        }
        for (int n = 0; n < 128; n++) {
            float acc = b2[n];
            const __nv_bfloat16* w = w2t + (size_t)n * HH1;
            for (int k = 0; k < HH1; k++)
                acc += __bfloat162float(__float2bfloat16(h1[k])) * __bfloat162float(w[k]);
            h2[n] = fmaxf(acc, 0.f);
        }
        for (int n = 0; n < 64; n++) {
            float acc = b3[n];
            const __nv_bfloat16* w = w3t + (size_t)n * HH2;
            for (int k = 0; k < HH2; k++)
                acc += __bfloat162float(__float2bfloat16(h2[k])) * __bfloat162float(w[k]);
            d[n] = acc;
        }
        const float tinv = 1.0f / temp_of((float)(*epochp));
        float mx = -1e30f;
        for (int j = 0; j < 64; j++) {
            d[j] = (d[j] - __logf(-__logf(u[(size_t)row * 64 + j]))) * tinv;
            mx = fmaxf(mx, d[j]);
        }
        float sum = 0.f;
        for (int j = 0; j < 64; j++) { d[j] = __expf(d[j] - mx); sum += d[j]; }
        float rs = 1.0f / sum, sel = 0.f;
        for (int j = 0; j < 64; j++) {
            float xtv = b3 ? 0.f : 0.f; // placeholder keeps signature use
            (void)xtv;
            float acc = 0.f;
            const __nv_bfloat16* w = tt + (size_t)j * DD;
            for (int k = 0; k < DD; k++)
                acc += __bfloat162float(__float2bfloat16(x[(size_t)row * DD + k])) * __bfloat162float(w[k]);
            sel = fmaf(acc, d[j] * rs, sel);
        }
        float diff = sel - label[row];
        p = diff * diff * (1.0f / (float)BB);
    }
    for (int o = 16; o; o >>= 1) p += __shfl_xor_sync(0xffffffffu, p, o);
    if ((tid & 31) == 0) red[tid >> 5] = p;
    __syncthreads();
    if (tid == 0) {
        float s = 0.f;
        for (int w = 0; w < 8; w++) s += red[w];
        atomicAdd(out, s);
    }
#endif
}

// ---------------------------------------------------------------------------
extern "C" void kernel_launch(void* const* d_in, const int* in_sizes, int n_in,
                              void* d_out, int out_size)
{
    const float* x      = (const float*)d_in[0];
    const float* label  = (const float*)d_in[1];
    const float* u      = (const float*)d_in[2];
    const float* W1     = (const float*)d_in[3];
    const float* b1     = (const float*)d_in[4];
    const float* W2     = (const float*)d_in[5];
    const float* b2     = (const float*)d_in[6];
    const float* W3     = (const float*)d_in[7];
    const float* b3     = (const float*)d_in[8];
    const float* thetas = (const float*)d_in[9];
    const int*   epoch  = (const int*)d_in[10];
    float* out = (float*)d_out;

    __nv_bfloat16 *w1t, *w2t, *w3t, *tt;
    cudaGetSymbolAddress((void**)&w1t, g_w1t);
    cudaGetSymbolAddress((void**)&w2t, g_w2t);
    cudaGetSymbolAddress((void**)&w3t, g_w3t);
    cudaGetSymbolAddress((void**)&tt,  g_tt);

    constexpr int SMEM = 132096;   // max(phase1 115712, phase2/3 132096)
    cudaFuncSetAttribute(fused_llp, cudaFuncAttributeMaxDynamicSharedMemorySize, SMEM);

    cudaMemsetAsync(out, 0, (size_t)out_size * sizeof(float), 0);

    transpose_all<<<800, 256>>>(W1, W2, W3, thetas, w1t, w2t, w3t, tt);

    fused_llp<<<BB / 128, 256, SMEM>>>(x, u, label, w1t, w2t, w3t, tt,
                                       b1, b2, b3, epoch, out);
}

// round 6
// speedup vs baseline: 7.9173x; 1.1076x over previous
#include <cuda_runtime.h>
#include <cuda_bf16.h>
#include <cstdint>

#ifndef __CUDA_ARCH_HAS_FEATURE__
#define __CUDA_ARCH_HAS_FEATURE__(x) 0
#endif
#if defined(__CUDA_ARCH_FEAT_SM103_ALL) || __CUDA_ARCH_HAS_FEATURE__(SM103_ALL) || \
    defined(__CUDA_ARCH_FEAT_SM100_ALL) || __CUDA_ARCH_HAS_FEATURE__(SM100_ALL)
#define HAS_TCGEN05 1
#else
#define HAS_TCGEN05 0
#endif

static constexpr int BB  = 65536;
static constexpr int DD  = 512;
static constexpr int KK  = 64;
static constexpr int HH1 = 256;
static constexpr int HH2 = 128;

__device__ __nv_bfloat16 g_w1t[HH1 * DD];
__device__ __nv_bfloat16 g_w2t[HH2 * HH1];
__device__ __nv_bfloat16 g_w3t[KK * HH2];
__device__ __nv_bfloat16 g_tt [KK * DD];

// ---------------- PTX helpers ----------------------------------------------
__device__ __forceinline__ uint32_t smem_u32(const void* p) {
    uint32_t a;
    asm("{ .reg .u64 t; cvta.to.shared.u64 t, %1; cvt.u32.u64 %0, t; }" : "=r"(a) : "l"(p));
    return a;
}
__device__ __forceinline__ uint32_t elect_one() {
    uint32_t pred;
    asm volatile("{\n\t.reg .pred p;\n\telect.sync _|p, 0xFFFFFFFF;\n\tselp.b32 %0, 1, 0, p;\n\t}" : "=r"(pred));
    return pred;
}
#define MBAR_INIT(addr, cnt) \
    asm volatile("mbarrier.init.shared.b64 [%0], %1;" :: "r"(addr), "r"(cnt) : "memory")
#define MBAR_WAIT(addr, parity) do {                                              \
    asm volatile("{\n\t.reg .pred P;\n\tWL%=:\n\t"                                \
        "mbarrier.try_wait.parity.acquire.cta.shared::cta.b64 P, [%0], %1, 0x989680;\n\t" \
        "@P bra.uni WD%=;\n\tbra.uni WL%=;\n\tWD%=:\n\t}"                          \
        :: "r"(addr), "r"(parity) : "memory");                                    \
} while (0)
#define TC_ALLOC(smem_dst, n) \
    asm volatile("tcgen05.alloc.cta_group::1.sync.aligned.shared::cta.b32 [%0], %1;" :: "r"(smem_dst), "r"(n) : "memory")
#define TC_DEALLOC(tmem, n) \
    asm volatile("tcgen05.dealloc.cta_group::1.sync.aligned.b32 %0, %1;" :: "r"(tmem), "r"(n))
#define TC_RELINQ() \
    asm volatile("tcgen05.relinquish_alloc_permit.cta_group::1.sync.aligned;")
#define TC_COMMIT(mbar) \
    asm volatile("tcgen05.commit.cta_group::1.mbarrier::arrive::one.shared::cluster.b64 [%0];" :: "r"(mbar) : "memory")
#define TC_FENCE_AFTER()  asm volatile("tcgen05.fence::after_thread_sync;" ::: "memory")
#define TC_WAIT_LD()      asm volatile("tcgen05.wait::ld.sync.aligned;" ::: "memory")

#define CP_ASYNC16(dst, src) \
    asm volatile("cp.async.cg.shared.global [%0], [%1], 16;" :: "r"(dst), "l"(src) : "memory")
#define CP_COMMIT() asm volatile("cp.async.commit_group;" ::: "memory")
#define CP_WAIT(n)  asm volatile("cp.async.wait_group %0;" :: "n"(n) : "memory")

#define TC_LD_X32(r, tmem_addr) \
    asm volatile( \
        "tcgen05.ld.sync.aligned.32x32b.x32.b32 " \
        "{%0, %1, %2, %3, %4, %5, %6, %7, " \
        " %8, %9, %10, %11, %12, %13, %14, %15, " \
        " %16, %17, %18, %19, %20, %21, %22, %23, " \
        " %24, %25, %26, %27, %28, %29, %30, %31}, [%32];" \
        : "=r"((r)[0]),  "=r"((r)[1]),  "=r"((r)[2]),  "=r"((r)[3]), \
          "=r"((r)[4]),  "=r"((r)[5]),  "=r"((r)[6]),  "=r"((r)[7]), \
          "=r"((r)[8]),  "=r"((r)[9]),  "=r"((r)[10]), "=r"((r)[11]), \
          "=r"((r)[12]), "=r"((r)[13]), "=r"((r)[14]), "=r"((r)[15]), \
          "=r"((r)[16]), "=r"((r)[17]), "=r"((r)[18]), "=r"((r)[19]), \
          "=r"((r)[20]), "=r"((r)[21]), "=r"((r)[22]), "=r"((r)[23]), \
          "=r"((r)[24]), "=r"((r)[25]), "=r"((r)[26]), "=r"((r)[27]), \
          "=r"((r)[28]), "=r"((r)[29]), "=r"((r)[30]), "=r"((r)[31]) \
        : "r"(tmem_addr))

#define TC_LD_X16(r, tmem_addr) \
    asm volatile( \
        "tcgen05.ld.sync.aligned.32x32b.x16.b32 " \
        "{%0, %1, %2, %3, %4, %5, %6, %7, " \
        " %8, %9, %10, %11, %12, %13, %14, %15}, [%16];" \
        : "=r"((r)[0]),  "=r"((r)[1]),  "=r"((r)[2]),  "=r"((r)[3]), \
          "=r"((r)[4]),  "=r"((r)[5]),  "=r"((r)[6]),  "=r"((r)[7]), \
          "=r"((r)[8]),  "=r"((r)[9]),  "=r"((r)[10]), "=r"((r)[11]), \
          "=r"((r)[12]), "=r"((r)[13]), "=r"((r)[14]), "=r"((r)[15]) \
        : "r"(tmem_addr))

#if HAS_TCGEN05
__device__ __forceinline__ void mma_f16_ss(uint32_t d, uint64_t ad, uint64_t bd,
                                           uint32_t idesc, uint32_t en) {
    asm volatile(
        "{\n\t.reg .pred p;\n\tsetp.ne.u32 p, %4, 0;\n\t"
        "tcgen05.mma.cta_group::1.kind::f16 [%0], %1, %2, %3, {%5, %5, %5, %5}, p;\n\t}"
        :: "r"(d), "l"(ad), "l"(bd), "r"(idesc), "r"(en), "r"(0u) : "memory");
}
#endif

__device__ __forceinline__ uint64_t make_desc(uint32_t addr) {
    const uint64_t base = (2ull << 61) | (1ull << 46) | (64ull << 32) | (1ull << 16);
    return base | ((uint64_t)(addr >> 4) & 0x3FFF);
}
__device__ __forceinline__ uint32_t sw128(uint32_t o) { return o ^ ((o >> 3) & 0x70); }

__device__ __forceinline__ uint32_t pack_bf2(float a, float b) {
    uint32_t r;
    asm("cvt.rn.satfinite.bf16x2.f32 %0, %1, %2;" : "=r"(r) : "f"(b), "f"(a));
    return r;
}

static __host__ __device__ constexpr uint32_t idesc_n(int N) {
    return (1u << 4) | (1u << 7) | (1u << 10) | ((uint32_t)(N / 8) << 17) | (8u << 24);
}

// ---- division-free FFMA ln / exp (keeps the MUFU pipe idle) -----------------
__device__ __forceinline__ float vlnf(float x) {
    int i = __float_as_int(x);
    float e = (float)((i >> 23) - 126);
    float m = __int_as_float((i & 0x007FFFFF) | 0x3F000000);   // [0.5, 1)
    if (m < 0.70710678f) { m += m; e -= 1.0f; }                // [sqrt(.5), sqrt2)
    float z = m - 1.0f;
    float w = z * z;
    float p =              7.0376836292e-2f;
    p = fmaf(p, z, -1.1514610310e-1f);
    p = fmaf(p, z,  1.1676998740e-1f);
    p = fmaf(p, z, -1.2420140846e-1f);
    p = fmaf(p, z,  1.4249322787e-1f);
    p = fmaf(p, z, -1.6668057665e-1f);
    p = fmaf(p, z,  2.0000714765e-1f);
    p = fmaf(p, z, -2.4999993993e-1f);
    p = fmaf(p, z,  3.3333331174e-1f);
    float r = fmaf(z * w, p, fmaf(-0.5f, w, z));
    return fmaf(e, 0.693147180559945f, r);
}
__device__ __forceinline__ float vexpf(float x) {
    float t = x * 1.4426950408889634f;
    t = fmaxf(t, -125.0f);
    int ni = __float2int_rn(t);
    float f = t - (float)ni;
    float p =              1.53533619e-4f;
    p = fmaf(p, f, 1.33988744e-3f);
    p = fmaf(p, f, 9.61843736e-3f);
    p = fmaf(p, f, 5.55033250e-2f);
    p = fmaf(p, f, 2.40226479e-1f);
    p = fmaf(p, f, 6.93147203e-1f);
    p = fmaf(p, f, 1.0f);
    return p * __int_as_float((ni + 127) << 23);
}

__device__ __forceinline__ float temp_of(float ep) {
    float t = 10.0f * vexpf(-4.60517018598809f * ep * 0.001f);  // ln(0.01)
    return fmaxf(0.1f, t);
}

// ---------------- weight transpose + bf16 convert (one launch) ---------------
__global__ void transpose_all(const float* __restrict__ W1, const float* __restrict__ W2,
                              const float* __restrict__ W3, const float* __restrict__ Th,
                              __nv_bfloat16* __restrict__ w1t, __nv_bfloat16* __restrict__ w2t,
                              __nv_bfloat16* __restrict__ w3t, __nv_bfloat16* __restrict__ tt)
{
    int idx = blockIdx.x * 256 + threadIdx.x;
    if (idx < 131072) {
        int r = idx >> 8, c = idx & 255;
        w1t[c * DD + r] = __float2bfloat16(W1[idx]);
    } else if (idx < 163840) {
        int q = idx - 131072; int r = q >> 7, c = q & 127;
        w2t[c * HH1 + r] = __float2bfloat16(W2[q]);
    } else if (idx < 172032) {
        int q = idx - 163840; int r = q >> 6, c = q & 63;
        w3t[c * HH2 + r] = __float2bfloat16(W3[q]);
    } else if (idx < 204800) {
        int q = idx - 172032; int r = q >> 6, c = q & 63;
        tt[c * DD + r] = __float2bfloat16(Th[q]);
    }
}

// ---------------- SMEM map (bytes from dynamic base) -------------------------
//  0       tmem ptr        8/16/24 mbarriers     256 b1[256] 1280 b2[128] 1792 b3[64]
//  2048    red[16]
//  phase1: STG fp32 3x32KB @4096    ATILE bf16 2x16KB @102400   BTILE 2x40KB @135168
//  phase2+ (reuse): H1 @4096(64KB)  W2T @69632(64KB)  H2 @135168(32KB)  W3T @167936(16KB)
//  U (272B/row pad) @180224(34816)  LABEL @215040(512)
//  PMAX @215552  PSUM @217600  PDOT @219648   end 221696
static constexpr int SMEM_SIZE = 221696;

__global__ __launch_bounds__(512, 1) void fused_llp(
    const float* __restrict__ x, const float* __restrict__ u,
    const float* __restrict__ label,
    const __nv_bfloat16* __restrict__ w1t, const __nv_bfloat16* __restrict__ w2t,
    const __nv_bfloat16* __restrict__ w3t, const __nv_bfloat16* __restrict__ tt,
    const float* __restrict__ b1, const float* __restrict__ b2,
    const float* __restrict__ b3, const int* __restrict__ epochp,
    float* __restrict__ out)
{
#if HAS_TCGEN05
    constexpr uint32_t MB0 = 8, MB1 = 16, MB2 = 24;
    constexpr uint32_t B1OFF = 256, B2OFF = 1280, B3OFF = 1792, RED = 2048;
    constexpr uint32_t STGB = 4096, ATB = 102400, BTB = 135168;
    constexpr uint32_t H1T = 4096, W2T = 69632, H2T = 135168, W3T = 167936;
    constexpr uint32_t UOF = 180224, LBL = 215040;
    constexpr uint32_t PMX = 215552, PSM = 217600, PDT = 219648;
    constexpr uint32_t IDB1 = idesc_n(256), IDT = idesc_n(64);
    constexpr uint32_t IDB2 = idesc_n(128), IDB3 = idesc_n(64);
    constexpr uint32_t T_H1 = 0, T_XT = 256, T_H2 = 320, T_LG = 448;

    extern __shared__ char smem[];
    const uint32_t sb = smem_u32(smem);
    const int tid = threadIdx.x;
    const int wid = tid >> 5;
    const int lane = tid & 31;
    const int m0 = blockIdx.x * 128;

    if (wid == 0) TC_ALLOC(sb + 0, 512);
    if (tid == 0) { MBAR_INIT(sb + MB0, 1); MBAR_INIT(sb + MB1, 1); MBAR_INIT(sb + MB2, 1); }
    // biases to smem
    if (tid < 256) ((float*)(smem + B1OFF))[tid] = b1[tid];
    else if (tid < 384) ((float*)(smem + B2OFF))[tid - 256] = b2[tid - 256];
    else if (tid < 448) ((float*)(smem + B3OFF))[tid - 384] = b3[tid - 384];
    __syncthreads();
    uint32_t tmem;
    asm volatile("ld.shared.b32 %0, [%1];" : "=r"(tmem) : "r"(sb + 0));

    // -------- phase 1: x @ [W1t|tt], K=512, 8 chunks, 3-stage cp.async ------
    auto issue_A = [&](int c) {
        const uint32_t stg = STGB + (uint32_t)(c % 3) * 32768u;
#pragma unroll
        for (int i = 0; i < 4; i++) {
            int q = tid + i * 512;
            int row = q >> 4, seg = q & 15;
            CP_ASYNC16(sb + stg + row * 256 + seg * 16,
                       x + (size_t)(m0 + row) * DD + c * 64 + seg * 4);
        }
        CP_COMMIT();
    };
    issue_A(0); issue_A(1); issue_A(2);

    for (int c = 0; c < 8; c++) {
        const int bufsel = c & 1;
        const uint32_t at = ATB + (uint32_t)bufsel * 16384u;
        const uint32_t bt = BTB + (uint32_t)bufsel * 40960u;
        if (c >= 2) MBAR_WAIT(sb + MB0 + 8 * bufsel, ((c - 2) >> 1) & 1);

        // B tile (LDG -> STS, L2-hot weights)
#pragma unroll
        for (int i = 0; i < 5; i++) {
            int q = tid + i * 512;
            int row = q >> 3, ku = q & 7;
            const __nv_bfloat16* src = (row >= 256) ? (tt + (size_t)(row - 256) * DD)
                                                    : (w1t + (size_t)row * DD);
            uint4 v = *(const uint4*)(src + c * 64 + ku * 8);
            *(uint4*)(smem + bt + sw128(row * 128 + ku * 16)) = v;
        }

        // staged A for chunk c must be resident
        if (c <= 5) CP_WAIT(2); else if (c == 6) CP_WAIT(1); else CP_WAIT(0);
        __syncthreads();

        // convert fp32 staging -> bf16 A tile (swizzled)
        {
            const uint32_t stg = STGB + (uint32_t)(c % 3) * 32768u;
            int row = tid >> 2, s = tid & 3;
            const float4* sp = (const float4*)(smem + stg + row * 256 + s * 64);
            float4 f0 = sp[0], f1 = sp[1], f2 = sp[2], f3 = sp[3];
            uint4 v0 = make_uint4(pack_bf2(f0.x, f0.y), pack_bf2(f0.z, f0.w),
                                  pack_bf2(f1.x, f1.y), pack_bf2(f1.z, f1.w));
            uint4 v1 = make_uint4(pack_bf2(f2.x, f2.y), pack_bf2(f2.z, f2.w),
                                  pack_bf2(f3.x, f3.y), pack_bf2(f3.z, f3.w));
            uint32_t base = row * 128 + s * 32;
            *(uint4*)(smem + at + sw128(base)) = v0;
            *(uint4*)(smem + at + sw128(base + 16)) = v1;
        }
        asm volatile("fence.proxy.async.shared::cta;" ::: "memory");
        __syncthreads();

        if (c + 3 <= 7) issue_A(c + 3);   // staging slot (c%3) now free

        if (wid == 0 && elect_one()) {
            uint64_t ad = make_desc(sb + at);
            uint64_t bd = make_desc(sb + bt);
            uint64_t td = make_desc(sb + bt + 256 * 128);
#pragma unroll
            for (int s = 0; s < 4; s++) {
                uint32_t en = (c > 0 || s > 0) ? 1u : 0u;
                mma_f16_ss(tmem + T_H1, ad + 2 * s, bd + 2 * s, IDB1, en);
                mma_f16_ss(tmem + T_XT, ad + 2 * s, td + 2 * s, IDT, en);
            }
            TC_COMMIT(sb + MB0 + 8 * bufsel);
        }
        __syncwarp();
    }
    MBAR_WAIT(sb + MB1, 1);
    TC_FENCE_AFTER();
    __syncthreads();

    // -------- phase 2: h1 epilogue -> SMEM, load W2T, prefetch u/label ------
    {
        const int g = wid >> 2;
        const int tr = (wid & 3) * 32 + lane;
        const float* sb1 = (const float*)(smem + B1OFF);
#pragma unroll
        for (int ch = 0; ch < 2; ch++) {
            const int cb = g * 64 + ch * 32;
            uint32_t r[32];
            TC_LD_X32(r, tmem + T_H1 + cb);
            TC_WAIT_LD();
            uint32_t pk[16];
#pragma unroll
            for (int i = 0; i < 16; i++) {
                float a = __uint_as_float(r[2 * i + 0]) + sb1[cb + 2 * i + 0];
                float b = __uint_as_float(r[2 * i + 1]) + sb1[cb + 2 * i + 1];
                pk[i] = pack_bf2(fmaxf(a, 0.f), fmaxf(b, 0.f));
            }
            const uint32_t blk = (uint32_t)(cb >> 6) * 16384u;
            const uint32_t base = (uint32_t)tr * 128 + (uint32_t)(cb & 63) * 2;
#pragma unroll
            for (int k = 0; k < 4; k++)
                *(uint4*)(smem + H1T + blk + sw128(base + k * 16)) =
                    make_uint4(pk[4 * k], pk[4 * k + 1], pk[4 * k + 2], pk[4 * k + 3]);
        }
        // W2T: 128x256 bf16 (4 K-blocks of 128x64)
#pragma unroll
        for (int i = 0; i < 8; i++) {
            int q = tid + i * 512;
            int n = q >> 5, t = q & 31, blk = t >> 3, ku = t & 7;
            uint4 v = *(const uint4*)(w2t + (size_t)n * HH1 + blk * 64 + ku * 8);
            *(uint4*)(smem + W2T + blk * 16384 + sw128(n * 128 + ku * 16)) = v;
        }
        // prefetch u (padded 272B rows) + label
#pragma unroll
        for (int i = 0; i < 4; i++) {
            int q = tid + i * 512;
            int row = q >> 4, seg = q & 15;
            CP_ASYNC16(sb + UOF + row * 272 + seg * 16,
                       u + (size_t)(m0 + row) * 64 + seg * 4);
        }
        if (tid < 32) CP_ASYNC16(sb + LBL + tid * 16, label + m0 + tid * 4);
        CP_COMMIT();
    }
    asm volatile("fence.proxy.async.shared::cta;" ::: "memory");
    __syncthreads();

    // -------- phase 3: h1 @ W2t -> h2, K=256 --------------------------------
    if (wid == 0 && elect_one()) {
        uint64_t ad = make_desc(sb + H1T);
        uint64_t bd = make_desc(sb + W2T);
#pragma unroll
        for (int s = 0; s < 16; s++) {
            uint64_t off = (uint64_t)(s >> 2) * 1024 + (s & 3) * 2;
            mma_f16_ss(tmem + T_H2, ad + off, bd + off, IDB2, s > 0 ? 1u : 0u);
        }
        TC_COMMIT(sb + MB2);
    }
    MBAR_WAIT(sb + MB2, 0);
    TC_FENCE_AFTER();
    __syncthreads();

    // -------- phase 4: h2 epilogue -> SMEM (warps 0-7), W3T (warps 8-15) ----
    {
        const float* sb2 = (const float*)(smem + B2OFF);
        if (wid < 8) {
            const int g = wid >> 2;
            const int tr = (wid & 3) * 32 + lane;
#pragma unroll
            for (int ch = 0; ch < 2; ch++) {
                const int cb = g * 64 + ch * 32;
                uint32_t r[32];
                TC_LD_X32(r, tmem + T_H2 + cb);
                TC_WAIT_LD();
                uint32_t pk[16];
#pragma unroll
                for (int i = 0; i < 16; i++) {
                    float a = __uint_as_float(r[2 * i + 0]) + sb2[cb + 2 * i + 0];
                    float b = __uint_as_float(r[2 * i + 1]) + sb2[cb + 2 * i + 1];
                    pk[i] = pack_bf2(fmaxf(a, 0.f), fmaxf(b, 0.f));
                }
                const uint32_t blk = (uint32_t)(cb >> 6) * 16384u;
                const uint32_t base = (uint32_t)tr * 128 + (uint32_t)(cb & 63) * 2;
#pragma unroll
                for (int k = 0; k < 4; k++)
                    *(uint4*)(smem + H2T + blk + sw128(base + k * 16)) =
                        make_uint4(pk[4 * k], pk[4 * k + 1], pk[4 * k + 2], pk[4 * k + 3]);
            }
        } else {
            // W3T: 64x128 bf16 (2 K-blocks of 64x64)
            int lt = tid - 256;
#pragma unroll
            for (int i = 0; i < 4; i++) {
                int q = lt + i * 256;
                int n = q >> 4, t = q & 15, blk = t >> 3, ku = t & 7;
                uint4 v = *(const uint4*)(w3t + (size_t)n * HH2 + blk * 64 + ku * 8);
                *(uint4*)(smem + W3T + blk * 8192 + sw128(n * 128 + ku * 16)) = v;
            }
        }
    }
    asm volatile("fence.proxy.async.shared::cta;" ::: "memory");
    __syncthreads();

    // -------- phase 5: h2 @ W3t -> logits, K=128 ----------------------------
    if (wid == 0 && elect_one()) {
        uint64_t ad = make_desc(sb + H2T);
        uint64_t bd = make_desc(sb + W3T);
#pragma unroll
        for (int s = 0; s < 8; s++) {
            uint64_t aoff = (uint64_t)(s >> 2) * 1024 + (s & 3) * 2;
            uint64_t boff = (uint64_t)(s >> 2) * 512 + (s & 3) * 2;
            mma_f16_ss(tmem + T_LG, ad + aoff, bd + boff, IDB3, s > 0 ? 1u : 0u);
        }
        TC_COMMIT(sb + MB2);
    }
    MBAR_WAIT(sb + MB2, 1);
    TC_FENCE_AFTER();
    CP_WAIT(0);
    __syncthreads();

    // -------- phase 6: gumbel softmax + <xt,w> + MSE (all 16 warps) ---------
    {
        const int g = wid >> 2;                   // column group (16 cols each)
        const int tr = (wid & 3) * 32 + lane;     // tile row (TMEM subpartition)
        const float* sb3 = (const float*)(smem + B3OFF);
        float* pmax = (float*)(smem + PMX);
        float* psum = (float*)(smem + PSM);
        float* pdot = (float*)(smem + PDT);

        float s[16], xtv[16];
        {
            uint32_t r[16];
            TC_LD_X16(r, tmem + T_LG + g * 16);
            TC_WAIT_LD();
#pragma unroll
            for (int j = 0; j < 16; j++) s[j] = __uint_as_float(r[j]) + sb3[g * 16 + j];
            TC_LD_X16(r, tmem + T_XT + g * 16);
            TC_WAIT_LD();
#pragma unroll
            for (int j = 0; j < 16; j++) xtv[j] = __uint_as_float(r[j]);
        }
        const float tinv = 1.0f / temp_of((float)(*epochp));
        const float* urow = (const float*)(smem + UOF + tr * 272);
        float mx = -1e30f;
#pragma unroll
        for (int j = 0; j < 16; j++) {
            float uu = urow[g * 16 + j];
            float gum = -vlnf(-vlnf(uu));
            s[j] = (s[j] + gum) * tinv;
            mx = fmaxf(mx, s[j]);
        }
        pmax[tr * 4 + g] = mx;
        __syncthreads();
        float4 m4 = *(const float4*)&pmax[tr * 4];
        mx = fmaxf(fmaxf(m4.x, m4.y), fmaxf(m4.z, m4.w));
        float sum = 0.f, dot = 0.f;
#pragma unroll
        for (int j = 0; j < 16; j++) {
            float e = vexpf(s[j] - mx);
            sum += e;
            dot = fmaf(xtv[j], e, dot);
        }
        psum[tr * 4 + g] = sum;
        pdot[tr * 4 + g] = dot;
        __syncthreads();

        float p = 0.f;
        if (wid < 4) {
            float4 s4 = *(const float4*)&psum[tr * 4];
            float4 d4 = *(const float4*)&pdot[tr * 4];
            float tsum = (s4.x + s4.y) + (s4.z + s4.w);
            float tdot = (d4.x + d4.y) + (d4.z + d4.w);
            float sel = tdot / tsum;
            float lb = ((const float*)(smem + LBL))[tr];
            float diff = sel - lb;
            p = diff * diff * (1.0f / (float)BB);
        }
#pragma unroll
        for (int o = 16; o; o >>= 1) p += __shfl_xor_sync(0xffffffffu, p, o);
        float* red = (float*)(smem + RED);
        if (wid < 4 && lane == 0) red[wid] = p;
        __syncthreads();
        if (tid == 0) atomicAdd(out, red[0] + red[1] + red[2] + red[3]);
    }

    __syncthreads();
    if (wid == 0) { TC_RELINQ(); TC_DEALLOC(tmem, 512); }

#else  // ------------------- SIMT fallback (generic PTX pass only) ----------
    __shared__ float red[16];
    const int tid = threadIdx.x;
    const int m0 = blockIdx.x * 128;
    float p = 0.f;
    if (tid < 128) {
        const int row = m0 + tid;
        float h1[256], h2[128], d[64];
        for (int n = 0; n < 256; n++) {
            float acc = b1[n];
            const __nv_bfloat16* w = w1t + (size_t)n * DD;
            for (int k = 0; k < DD; k++)
                acc += __bfloat162float(__float2bfloat16(x[(size_t)row * DD + k])) * __bfloat162float(w[k]);
            h1[n] = fmaxf(acc, 0.f);
        }
        for (int n = 0; n < 128; n++) {
            float acc = b2[n];
            const __nv_bfloat16* w = w2t + (size_t)n * HH1;
            for (int k = 0; k < HH1; k++)
                acc += __bfloat162float(__float2bfloat16(h1[k])) * __bfloat162float(w[k]);
            h2[n] = fmaxf(acc, 0.f);
        }
        for (int n = 0; n < 64; n++) {
            float acc = b3[n];
            const __nv_bfloat16* w = w3t + (size_t)n * HH2;
            for (int k = 0; k < HH2; k++)
                acc += __bfloat162float(__float2bfloat16(h2[k])) * __bfloat162float(w[k]);
            d[n] = acc;
        }
        const float tinv = 1.0f / temp_of((float)(*epochp));
        float mx = -1e30f;
        for (int j = 0; j < 64; j++) {
            d[j] = (d[j] - vlnf(-vlnf(u[(size_t)row * 64 + j]))) * tinv;
            mx = fmaxf(mx, d[j]);
        }
        float sum = 0.f;
        for (int j = 0; j < 64; j++) { d[j] = vexpf(d[j] - mx); sum += d[j]; }
        float rs = 1.0f / sum, sel = 0.f;
        for (int j = 0; j < 64; j++) {
            float acc = 0.f;
            const __nv_bfloat16* w = tt + (size_t)j * DD;
            for (int k = 0; k < DD; k++)
                acc += __bfloat162float(__float2bfloat16(x[(size_t)row * DD + k])) * __bfloat162float(w[k]);
            sel = fmaf(acc, d[j] * rs, sel);
        }
        float diff = sel - label[row];
        p = diff * diff * (1.0f / (float)BB);
    }
    for (int o = 16; o; o >>= 1) p += __shfl_xor_sync(0xffffffffu, p, o);
    if ((tid & 31) == 0) red[tid >> 5] = p;
    __syncthreads();
    if (tid == 0) {
        float s = 0.f;
        for (int w = 0; w < 16; w++) s += red[w];
        atomicAdd(out, s);
    }
#endif
}

// ---------------------------------------------------------------------------
extern "C" void kernel_launch(void* const* d_in, const int* in_sizes, int n_in,
                              void* d_out, int out_size)
{
    const float* x      = (const float*)d_in[0];
    const float* label  = (const float*)d_in[1];
    const float* u      = (const float*)d_in[2];
    const float* W1     = (const float*)d_in[3];
    const float* b1     = (const float*)d_in[4];
    const float* W2     = (const float*)d_in[5];
    const float* b2     = (const float*)d_in[6];
    const float* W3     = (const float*)d_in[7];
    const float* b3     = (const float*)d_in[8];
    const float* thetas = (const float*)d_in[9];
    const int*   epoch  = (const int*)d_in[10];
    float* out = (float*)d_out;

    __nv_bfloat16 *w1t, *w2t, *w3t, *tt;
    cudaGetSymbolAddress((void**)&w1t, g_w1t);
    cudaGetSymbolAddress((void**)&w2t, g_w2t);
    cudaGetSymbolAddress((void**)&w3t, g_w3t);
    cudaGetSymbolAddress((void**)&tt,  g_tt);

    cudaFuncSetAttribute(fused_llp, cudaFuncAttributeMaxDynamicSharedMemorySize, SMEM_SIZE);

    cudaMemsetAsync(out, 0, (size_t)out_size * sizeof(float), 0);

    transpose_all<<<800, 256>>>(W1, W2, W3, thetas, w1t, w2t, w3t, tt);

    fused_llp<<<BB / 128, 512, SMEM_SIZE>>>(x, u, label, w1t, w2t, w3t, tt,
                                            b1, b2, b3, epoch, out);
}